// round 7
// baseline (speedup 1.0000x reference)
#include <cuda_runtime.h>
#include <cuda_bf16.h>

// Problem constants
#define B_  16
#define C_  4096
#define HD_ 1024   // H*D
#define F_  1024

// One block owns 8 f-columns and the FULL K reduction.
// 256 threads = 8 f-lanes x 32 k-chunks (32 k each). Grid = 128 blocks.
#define FPB   8
#define KCHK  32
#define KPT   32     // k's per thread
#define NBLK  (F_ / FPB)   // 128

__device__ __forceinline__ void ffma2(unsigned long long& d,
                                      unsigned long long a,
                                      unsigned long long b) {
    asm("fma.rn.f32x2 %0, %1, %2, %0;" : "+l"(d) : "l"(a), "l"(b));
}
__device__ __forceinline__ unsigned long long pack2(float lo, float hi) {
    unsigned long long r;
    asm("mov.b64 %0, {%1, %2};" : "=l"(r) : "f"(lo), "f"(hi));
    return r;
}
__device__ __forceinline__ float unpack_sum(unsigned long long v) {
    float lo, hi;
    asm("mov.b64 {%0, %1}, %2;" : "=f"(lo), "=f"(hi) : "l"(v));
    return lo + hi;
}

// ---------------------------------------------------------------------------
// Single kernel, no cross-block communication.
// Attention degenerates (T=1 causal => softmax one-hot at rotated position 0)
// to v_sel[b] = bf16(kv_value[b, start_b]) -- or the fresh x@wv+bv row iff
// idx==0. Then y = v_sel @ wo + bo, each block reducing its own K in-block.
// ---------------------------------------------------------------------------
__global__ void __launch_bounds__(256)
fused_kernel(const float* __restrict__ x,
             const int*   __restrict__ kv_idx,
             const float* __restrict__ kv_value,
             const float* __restrict__ wv,
             const float* __restrict__ bv,
             const float* __restrict__ wo,
             const float* __restrict__ bo,
             float* __restrict__ y)
{
    extern __shared__ float vsm[];          // [B_][HD_] f32, 64 KB
    __shared__ float part[8][FPB][B_];      // per-warp partials, 4 KB
    __shared__ int   s_start[B_];
    __shared__ int   s_new[B_];

    const int tid   = threadIdx.x;
    const int fl    = tid & (FPB - 1);      // f within block: 0..7
    const int kc    = tid >> 3;             // k-chunk: 0..31
    const int k0    = kc * KPT;
    const int fbase = blockIdx.x * FPB;
    const int f     = fbase + fl;
    const int wrp   = tid >> 5;
    const int lane  = tid & 31;

    if (tid < B_) {
        const int idx     = kv_idx[tid];
        const int new_idx = idx + 1;
        const int start   = (new_idx <= C_) ? 0 : (new_idx % C_);
        s_start[tid] = start;
        s_new[tid]   = (start == (idx % C_));   // only when idx == 0
    }
    __syncthreads();

    // ---- Stage v_sel into smem, bf16-rounded. 4096 float4 / 256 thr ----
    #pragma unroll
    for (int j = 0; j < 16; j++) {
        const int i  = j * 256 + tid;       // float4 index, 0..4095
        const int b  = i >> 8;              // 256 float4 per row
        const int kq = i & 255;
        if (!s_new[b]) {
            const float4 v = __ldg(reinterpret_cast<const float4*>(
                kv_value + ((size_t)b * C_ + s_start[b]) * HD_) + kq);
            float4 r;
            r.x = __bfloat162float(__float2bfloat16(v.x));
            r.y = __bfloat162float(__float2bfloat16(v.y));
            r.z = __bfloat162float(__float2bfloat16(v.z));
            r.w = __bfloat162float(__float2bfloat16(v.w));
            reinterpret_cast<float4*>(vsm + b * HD_)[kq] = r;
        }
    }
    // Rare fallback (idx==0): fresh row = x[b] @ wv + bv (4 cols/thread)
    for (int b = 0; b < B_; b++) {
        if (s_new[b]) {
            #pragma unroll
            for (int c = 0; c < 4; c++) {
                const int j = c * 256 + tid;
                float acc = bv[j];
                for (int ff = 0; ff < F_; ff++)
                    acc = fmaf(__ldg(&x[b * F_ + ff]),
                               __ldg(&wv[(size_t)ff * HD_ + j]), acc);
                vsm[b * HD_ + j] = __bfloat162float(__float2bfloat16(acc));
            }
        }
    }
    __syncthreads();

    // ---- Main loop: this thread's 32 k's, all 16 b, packed f32x2 FMA ----
    unsigned long long acc2[B_];
    #pragma unroll
    for (int b = 0; b < B_; b++) acc2[b] = 0ull;

    #pragma unroll
    for (int k4 = 0; k4 < KPT; k4 += 4) {
        const float w0 = __ldg(&wo[(size_t)(k0 + k4 + 0) * F_ + f]);
        const float w1 = __ldg(&wo[(size_t)(k0 + k4 + 1) * F_ + f]);
        const float w2 = __ldg(&wo[(size_t)(k0 + k4 + 2) * F_ + f]);
        const float w3 = __ldg(&wo[(size_t)(k0 + k4 + 3) * F_ + f]);
        const unsigned long long wA = pack2(w0, w1);
        const unsigned long long wB = pack2(w2, w3);
        #pragma unroll
        for (int b = 0; b < B_; b++) {
            const float4 v = *reinterpret_cast<const float4*>(
                vsm + b * HD_ + k0 + k4);
            ffma2(acc2[b], pack2(v.x, v.y), wA);
            ffma2(acc2[b], pack2(v.z, v.w), wB);
        }
    }

    // ---- Reduce over k-chunks: 2 shuffle rounds (4 kc per warp) ----
    float acc[B_];
    #pragma unroll
    for (int b = 0; b < B_; b++) {
        float a = unpack_sum(acc2[b]);
        a += __shfl_xor_sync(0xffffffffu, a, 8);
        a += __shfl_xor_sync(0xffffffffu, a, 16);
        acc[b] = a;
    }
    if (lane < FPB) {                   // kc_local == 0 lanes hold warp sums
        #pragma unroll
        for (int b = 0; b < B_; b++)
            part[wrp][fl][b] = acc[b];
    }
    __syncthreads();

    // ---- Final: 128 threads, one output each; sum 8 warp partials ----
    if (tid < FPB * B_) {
        const int b  = tid >> 3;        // consecutive tid -> consecutive f
        const int ff = tid & (FPB - 1);
        float s = __ldg(&bo[fbase + ff]);
        #pragma unroll
        for (int w = 0; w < 8; w++)
            s += part[w][ff][b];
        y[b * F_ + fbase + ff] = s;
    }
}

// ---------------------------------------------------------------------------
// Inputs (metadata order): x, mask, kv_idx, kv_key, kv_value,
//                          wq, bq, wk, bk, wv, bv, wo, bo
// ---------------------------------------------------------------------------
extern "C" void kernel_launch(void* const* d_in, const int* in_sizes, int n_in,
                              void* d_out, int out_size)
{
    const float* x        = (const float*)d_in[0];
    const int*   kv_idx   = (const int*)  d_in[2];
    const float* kv_value = (const float*)d_in[4];
    const float* wv       = (const float*)d_in[9];
    const float* bv       = (const float*)d_in[10];
    const float* wo       = (const float*)d_in[11];
    const float* bo       = (const float*)d_in[12];
    float* y = (float*)d_out;

    const int smem = B_ * HD_ * sizeof(float);   // 64 KB dynamic
    static bool attr_done = false;
    if (!attr_done) {
        cudaFuncSetAttribute(fused_kernel,
                             cudaFuncAttributeMaxDynamicSharedMemorySize, smem);
        attr_done = true;
    }

    fused_kernel<<<NBLK, 256, smem>>>(x, kv_idx, kv_value,
                                      wv, bv, wo, bo, y);
}

// round 8
// speedup vs baseline: 1.1506x; 1.1506x over previous
#include <cuda_runtime.h>
#include <cuda_bf16.h>

// Problem constants
#define B_  16
#define C_  4096
#define HD_ 1024   // H*D
#define F_  1024

// Tiling: grid = (NF, NK) = 128 blocks, 256 threads (128 f-lanes x 2 b-halves)
#define NF  8
#define TFX 128
#define NK  16
#define TK  64
#define BH  8

// Monotonic per-f-tile counters (never reset -> graph-replay-safe).
// Each execution consumes exactly one generation: writer (kx==0) bumps done,
// the 15 waiter blocks take tickets; gen = ticket / 15.
__device__ unsigned int g_done[NF];     // zero-init at module load
__device__ unsigned int g_ticket[NF];

__device__ __forceinline__ unsigned ld_acq_u32(const unsigned* p) {
    unsigned v;
    asm volatile("ld.global.acquire.gpu.u32 %0, [%1];" : "=r"(v) : "l"(p));
    return v;
}
__device__ __forceinline__ void redg_add_f32(float* p, float v) {
    asm volatile("red.global.add.f32 [%0], %1;" :: "l"(p), "f"(v) : "memory");
}

// ---------------------------------------------------------------------------
// Single kernel. Attention degenerates (T=1 causal => softmax one-hot at
// rotated position 0) to v_sel[b] = bf16(kv_value[b, start_b]) -- or the
// fresh x@wv+bv row iff idx==0. Then y = v_sel @ wo + bo via split-K:
//   kx==0 block of each f-tile STOREs bias + its partial (overwriting the
//   harness poison), releases done[fx]; the other blocks spin (after their
//   compute) and then red.global.add their partials into y. No second pass.
// ---------------------------------------------------------------------------
__global__ void __launch_bounds__(2 * TFX)
fused_kernel(const float* __restrict__ x,
             const int*   __restrict__ kv_idx,
             const float* __restrict__ kv_value,
             const float* __restrict__ wv,
             const float* __restrict__ bv,
             const float* __restrict__ wo,
             const float* __restrict__ bo,
             float* __restrict__ y)
{
    const int fx   = blockIdx.x;
    const int kx   = blockIdx.y;
    const int tid  = threadIdx.x;
    const int lane = tid & (TFX - 1);       // f within tile
    const int half = tid >> 7;              // 0 -> b[0,8), 1 -> b[8,16)
    const int b0   = half * BH;
    const int k0   = kx * TK;
    const int f    = fx * TFX + lane;

    __shared__ float vs[B_][TK];            // bf16-rounded selected v slice
    __shared__ int   s_start[B_];
    __shared__ int   s_new[B_];

    if (tid < B_) {
        const int idx     = kv_idx[tid];
        const int new_idx = idx + 1;
        const int start   = (new_idx <= C_) ? 0 : (new_idx % C_);
        s_start[tid] = start;
        s_new[tid]   = (start == (idx % C_));   // only when idx == 0
    }
    __syncthreads();

    // Gather vs[b][k]: 1024 elems / 256 threads = 4 independent loads each
    #pragma unroll
    for (int i = tid; i < B_ * TK; i += 2 * TFX) {
        const int b = i / TK, k = i % TK;
        if (!s_new[b]) {
            const float v = __ldg(
                &kv_value[((size_t)b * C_ + s_start[b]) * HD_ + k0 + k]);
            vs[b][k] = __bfloat162float(__float2bfloat16(v));
        }
    }
    // Rare fallback (idx==0): fresh row = x[b] @ wv + bv for this k-slice
    for (int b = 0; b < B_; b++) {
        if (s_new[b] && tid < TK) {
            const int j = k0 + tid;
            float acc = bv[j];
            for (int ff = 0; ff < F_; ff++)
                acc = fmaf(__ldg(&x[b * F_ + ff]),
                           __ldg(&wv[(size_t)ff * HD_ + j]), acc);
            vs[b][tid] = __bfloat162float(__float2bfloat16(acc));
        }
    }
    __syncthreads();

    // ---- Partial GEMM for this (f-tile, k-chunk, b-half) ----
    float acc[BH];
    #pragma unroll
    for (int b = 0; b < BH; b++) acc[b] = 0.0f;

    #pragma unroll
    for (int k4 = 0; k4 < TK; k4 += 4) {
        const float w0 = __ldg(&wo[(size_t)(k0 + k4 + 0) * F_ + f]);
        const float w1 = __ldg(&wo[(size_t)(k0 + k4 + 1) * F_ + f]);
        const float w2 = __ldg(&wo[(size_t)(k0 + k4 + 2) * F_ + f]);
        const float w3 = __ldg(&wo[(size_t)(k0 + k4 + 3) * F_ + f]);
        #pragma unroll
        for (int b = 0; b < BH; b++) {
            const float4 v = *reinterpret_cast<const float4*>(&vs[b0 + b][k4]);
            acc[b] = fmaf(v.x, w0,
                     fmaf(v.y, w1,
                     fmaf(v.z, w2,
                     fmaf(v.w, w3, acc[b]))));
        }
    }

    if (kx == 0) {
        // Writer: overwrite poison with bias + our partial, then release.
        const float bias = __ldg(&bo[f]);
        #pragma unroll
        for (int b = 0; b < BH; b++)
            y[(b0 + b) * F_ + f] = acc[b] + bias;
        __threadfence();            // release stores device-wide
        __syncthreads();            // whole block fenced
        if (tid == 0)
            atomicAdd(&g_done[fx], 1u);
    } else {
        // Waiter: take a generation ticket, await this replay's writer,
        // then fire-and-forget reductions into y.
        __shared__ unsigned s_target;
        if (tid == 0)
            s_target = atomicAdd(&g_ticket[fx], 1u) / (NK - 1) + 1u;
        __syncthreads();
        if (tid == 0) {
            while (ld_acq_u32(&g_done[fx]) < s_target)
                __nanosleep(32);
        }
        __syncthreads();            // all threads ordered after acquire
        #pragma unroll
        for (int b = 0; b < BH; b++)
            redg_add_f32(&y[(b0 + b) * F_ + f], acc[b]);
    }
}

// ---------------------------------------------------------------------------
// Inputs (metadata order): x, mask, kv_idx, kv_key, kv_value,
//                          wq, bq, wk, bk, wv, bv, wo, bo
// ---------------------------------------------------------------------------
extern "C" void kernel_launch(void* const* d_in, const int* in_sizes, int n_in,
                              void* d_out, int out_size)
{
    const float* x        = (const float*)d_in[0];
    const int*   kv_idx   = (const int*)  d_in[2];
    const float* kv_value = (const float*)d_in[4];
    const float* wv       = (const float*)d_in[9];
    const float* bv       = (const float*)d_in[10];
    const float* wo       = (const float*)d_in[11];
    const float* bo       = (const float*)d_in[12];
    float* y = (float*)d_out;

    fused_kernel<<<dim3(NF, NK), 2 * TFX>>>(x, kv_idx, kv_value,
                                            wv, bv, wo, bo, y);
}

// round 9
// speedup vs baseline: 1.3465x; 1.1702x over previous
#include <cuda_runtime.h>
#include <cuda_bf16.h>

// Problem constants
#define B_  16
#define C_  4096
#define HD_ 1024   // H*D
#define F_  1024

// Tiling: grid = (NF, NK) = 256 blocks, 128 threads, one f-column per thread
#define NF  8
#define TFX 128
#define NK  32
#define TK  32

// Monotonic per-f-tile counters (never reset -> graph-replay-safe).
__device__ unsigned int g_done[NF];     // zero-init at module load
__device__ unsigned int g_ticket[NF];

__device__ __forceinline__ unsigned ld_acq_u32(const unsigned* p) {
    unsigned v;
    asm volatile("ld.global.acquire.gpu.u32 %0, [%1];" : "=r"(v) : "l"(p));
    return v;
}
__device__ __forceinline__ void redg_add_f32(float* p, float v) {
    asm volatile("red.global.add.f32 [%0], %1;" :: "l"(p), "f"(v) : "memory");
}
__device__ __forceinline__ void ffma2(unsigned long long& d,
                                      unsigned long long a,
                                      unsigned long long b) {
    asm("fma.rn.f32x2 %0, %1, %2, %0;" : "+l"(d) : "l"(a), "l"(b));
}
__device__ __forceinline__ unsigned long long pack2(float lo, float hi) {
    unsigned long long r;
    asm("mov.b64 %0, {%1, %2};" : "=l"(r) : "f"(lo), "f"(hi));
    return r;
}
__device__ __forceinline__ float unpack_sum(unsigned long long v) {
    float lo, hi;
    asm("mov.b64 {%0, %1}, %2;" : "=f"(lo), "=f"(hi) : "l"(v));
    return lo + hi;
}

// ---------------------------------------------------------------------------
// Single kernel. Attention degenerates (T=1 causal => softmax one-hot at
// rotated position 0) to v_sel[b] = bf16(kv_value[b, start_b]) -- or the
// fresh x@wv+bv row iff idx==0. Then y = v_sel @ wo + bo via split-K:
//   kx==0 block of each f-tile STOREs bias + its partial (overwriting the
//   harness poison) and releases done[fx]; the other 31 blocks spin after
//   their compute, then red.global.add their partials into y directly.
// ---------------------------------------------------------------------------
__global__ void __launch_bounds__(TFX)
fused_kernel(const float* __restrict__ x,
             const int*   __restrict__ kv_idx,
             const float* __restrict__ kv_value,
             const float* __restrict__ wv,
             const float* __restrict__ bv,
             const float* __restrict__ wo,
             const float* __restrict__ bo,
             float* __restrict__ y)
{
    const int fx  = blockIdx.x;
    const int kx  = blockIdx.y;
    const int tid = threadIdx.x;
    const int k0  = kx * TK;
    const int f   = fx * TFX + tid;

    __shared__ float vs[B_][TK];            // bf16-rounded selected v slice
    __shared__ int   s_start[B_];
    __shared__ int   s_new[B_];

    // ---- Hoisted wo loads: in flight during gather + barrier ----
    float w[TK];
    #pragma unroll
    for (int k = 0; k < TK; k++)
        w[k] = __ldg(&wo[(size_t)(k0 + k) * F_ + f]);

    if (tid < B_) {
        const int idx     = kv_idx[tid];
        const int new_idx = idx + 1;
        const int start   = (new_idx <= C_) ? 0 : (new_idx % C_);
        s_start[tid] = start;
        s_new[tid]   = (start == (idx % C_));   // only when idx == 0
    }
    __syncthreads();

    // Gather vs[b][k]: 512 elems / 128 threads = 4 independent loads each
    #pragma unroll
    for (int i = tid; i < B_ * TK; i += TFX) {
        const int b = i / TK, k = i % TK;
        if (!s_new[b]) {
            const float v = __ldg(
                &kv_value[((size_t)b * C_ + s_start[b]) * HD_ + k0 + k]);
            vs[b][k] = __bfloat162float(__float2bfloat16(v));
        }
    }
    // Rare fallback (idx==0): fresh row = x[b] @ wv + bv for this k-slice
    for (int b = 0; b < B_; b++) {
        if (s_new[b] && tid < TK) {
            const int j = k0 + tid;
            float acc = bv[j];
            for (int ff = 0; ff < F_; ff++)
                acc = fmaf(__ldg(&x[b * F_ + ff]),
                           __ldg(&wv[(size_t)ff * HD_ + j]), acc);
            vs[b][tid] = __bfloat162float(__float2bfloat16(acc));
        }
    }
    __syncthreads();

    // ---- Main loop: pure LDS + packed f32x2 FMA (wo already in regs) ----
    unsigned long long acc2[B_];
    #pragma unroll
    for (int b = 0; b < B_; b++) acc2[b] = 0ull;

    #pragma unroll
    for (int k4 = 0; k4 < TK; k4 += 4) {
        const unsigned long long wA = pack2(w[k4 + 0], w[k4 + 1]);
        const unsigned long long wB = pack2(w[k4 + 2], w[k4 + 3]);
        #pragma unroll
        for (int b = 0; b < B_; b++) {
            const float4 v = *reinterpret_cast<const float4*>(&vs[b][k4]);
            ffma2(acc2[b], pack2(v.x, v.y), wA);
            ffma2(acc2[b], pack2(v.z, v.w), wB);
        }
    }

    float acc[B_];
    #pragma unroll
    for (int b = 0; b < B_; b++) acc[b] = unpack_sum(acc2[b]);

    // ---- Epilogue: writer stores bias+partial, waiters REDG into y ----
    if (kx == 0) {
        const float bias = __ldg(&bo[f]);
        #pragma unroll
        for (int b = 0; b < B_; b++)
            y[b * F_ + f] = acc[b] + bias;
        __threadfence();            // release stores device-wide
        __syncthreads();            // whole block fenced
        if (tid == 0)
            atomicAdd(&g_done[fx], 1u);
    } else {
        __shared__ unsigned s_target;
        if (tid == 0)
            s_target = atomicAdd(&g_ticket[fx], 1u) / (NK - 1) + 1u;
        __syncthreads();
        if (tid == 0) {
            while (ld_acq_u32(&g_done[fx]) < s_target)
                __nanosleep(32);
        }
        __syncthreads();            // all threads ordered after acquire
        #pragma unroll
        for (int b = 0; b < B_; b++)
            redg_add_f32(&y[b * F_ + f], acc[b]);
    }
}

// ---------------------------------------------------------------------------
// Inputs (metadata order): x, mask, kv_idx, kv_key, kv_value,
//                          wq, bq, wk, bk, wv, bv, wo, bo
// ---------------------------------------------------------------------------
extern "C" void kernel_launch(void* const* d_in, const int* in_sizes, int n_in,
                              void* d_out, int out_size)
{
    const float* x        = (const float*)d_in[0];
    const int*   kv_idx   = (const int*)  d_in[2];
    const float* kv_value = (const float*)d_in[4];
    const float* wv       = (const float*)d_in[9];
    const float* bv       = (const float*)d_in[10];
    const float* wo       = (const float*)d_in[11];
    const float* bo       = (const float*)d_in[12];
    float* y = (float*)d_out;

    fused_kernel<<<dim3(NF, NK), TFX>>>(x, kv_idx, kv_value,
                                        wv, bv, wo, bo, y);
}

// round 11
// speedup vs baseline: 1.5436x; 1.1463x over previous
#include <cuda_runtime.h>
#include <cuda_bf16.h>

// Problem constants
#define B_  16
#define C_  4096
#define HD_ 1024   // H*D
#define F_  1024

// Tiling: grid = (NF, NK) = 256 blocks, 128 threads, one f-column per thread
#define NF  8
#define TFX 128
#define NK  32
#define TK  32

// Monotonic per-f-tile counters (never reset -> graph-replay-safe).
__device__ unsigned int g_done[NF];     // zero-init at module load
__device__ unsigned int g_ticket[NF];

__device__ __forceinline__ unsigned ld_acq_u32(const unsigned* p) {
    unsigned v;
    asm volatile("ld.global.acquire.gpu.u32 %0, [%1];" : "=r"(v) : "l"(p));
    return v;
}
__device__ __forceinline__ void redg_add_f32(float* p, float v) {
    asm volatile("red.global.add.f32 [%0], %1;" :: "l"(p), "f"(v) : "memory");
}
__device__ __forceinline__ void ffma2(unsigned long long& d,
                                      unsigned long long a,
                                      unsigned long long b) {
    asm("fma.rn.f32x2 %0, %1, %2, %0;" : "+l"(d) : "l"(a), "l"(b));
}
__device__ __forceinline__ unsigned long long pack2(float lo, float hi) {
    unsigned long long r;
    asm("mov.b64 %0, {%1, %2};" : "=l"(r) : "f"(lo), "f"(hi));
    return r;
}
__device__ __forceinline__ float unpack_sum(unsigned long long v) {
    float lo, hi;
    asm("mov.b64 {%0, %1}, %2;" : "=f"(lo), "=f"(hi) : "l"(v));
    return lo + hi;
}

// ---------------------------------------------------------------------------
// Single kernel. Attention degenerates (T=1 causal => softmax one-hot at
// rotated position 0) to v_sel[b] = bf16(kv_value[b, start_b]) -- or the
// fresh x@wv+bv row iff idx==0. Then y = v_sel @ wo + bo via split-K.
// EARLY-RELEASE epilogue: the kx==0 block of each f-tile overwrites the
// harness poison with the bias FIRST THING and releases done[fx]; then ALL
// 32 blocks (writer included) red.global.add their partials into y. Waiters'
// spin overlaps their own compute and collapses to one L2 acquire-read.
// ---------------------------------------------------------------------------
__global__ void __launch_bounds__(TFX)
fused_kernel(const float* __restrict__ x,
             const int*   __restrict__ kv_idx,
             const float* __restrict__ kv_value,
             const float* __restrict__ wv,
             const float* __restrict__ bv,
             const float* __restrict__ wo,
             const float* __restrict__ bo,
             float* __restrict__ y)
{
    const int fx  = blockIdx.x;
    const int kx  = blockIdx.y;
    const int tid = threadIdx.x;
    const int k0  = kx * TK;
    const int f   = fx * TFX + tid;

    __shared__ float    vs[B_][TK];         // bf16-rounded selected v slice
    __shared__ int      s_start[B_];
    __shared__ int      s_new[B_];
    __shared__ unsigned s_target;

    // ---- Writer: publish bias into y immediately, then release ----
    if (kx == 0) {
        const float bias = __ldg(&bo[f]);
        #pragma unroll
        for (int b = 0; b < B_; b++)
            y[b * F_ + f] = bias;
        __threadfence();            // release bias stores device-wide
    } else if (tid == 0) {
        // Waiter: grab this replay's generation ticket up front
        s_target = atomicAdd(&g_ticket[fx], 1u) / (NK - 1) + 1u;
    }

    if (tid < B_) {
        const int idx     = kv_idx[tid];
        const int new_idx = idx + 1;
        const int start   = (new_idx <= C_) ? 0 : (new_idx % C_);
        s_start[tid] = start;
        s_new[tid]   = (start == (idx % C_));   // only when idx == 0
    }
    __syncthreads();                // covers bias-fence / ticket / s_start

    if (kx == 0 && tid == 0)
        atomicAdd(&g_done[fx], 1u); // release AFTER whole block fenced

    // ---- Hoisted wo loads: in flight during gather ----
    float w[TK];
    #pragma unroll
    for (int k = 0; k < TK; k++)
        w[k] = __ldg(&wo[(size_t)(k0 + k) * F_ + f]);

    // Gather vs[b][k]: 512 elems / 128 threads = 4 independent loads each
    #pragma unroll
    for (int i = tid; i < B_ * TK; i += TFX) {
        const int b = i / TK, k = i % TK;
        if (!s_new[b]) {
            const float v = __ldg(
                &kv_value[((size_t)b * C_ + s_start[b]) * HD_ + k0 + k]);
            vs[b][k] = __bfloat162float(__float2bfloat16(v));
        }
    }
    // Rare fallback (idx==0): fresh row = x[b] @ wv + bv for this k-slice
    for (int b = 0; b < B_; b++) {
        if (s_new[b] && tid < TK) {
            const int j = k0 + tid;
            float acc = bv[j];
            for (int ff = 0; ff < F_; ff++)
                acc = fmaf(__ldg(&x[b * F_ + ff]),
                           __ldg(&wv[(size_t)ff * HD_ + j]), acc);
            vs[b][tid] = __bfloat162float(__float2bfloat16(acc));
        }
    }
    __syncthreads();

    // ---- Main loop: pure LDS + packed f32x2 FMA (wo already in regs) ----
    unsigned long long acc2[B_];
    #pragma unroll
    for (int b = 0; b < B_; b++) acc2[b] = 0ull;

    #pragma unroll
    for (int k4 = 0; k4 < TK; k4 += 4) {
        const unsigned long long wA = pack2(w[k4 + 0], w[k4 + 1]);
        const unsigned long long wB = pack2(w[k4 + 2], w[k4 + 3]);
        #pragma unroll
        for (int b = 0; b < B_; b++) {
            const float4 v = *reinterpret_cast<const float4*>(&vs[b][k4]);
            ffma2(acc2[b], pack2(v.x, v.y), wA);
            ffma2(acc2[b], pack2(v.z, v.w), wB);
        }
    }

    // ---- Epilogue: ensure bias is published, then fire REDG partials ----
    if (kx != 0) {
        if (tid == 0) {
            while (ld_acq_u32(&g_done[fx]) < s_target)   // usually 1 read
                __nanosleep(32);
        }
        __syncthreads();            // all threads ordered after acquire
    }
    // Writer: same-thread store->red on same address is program-ordered.
    #pragma unroll
    for (int b = 0; b < B_; b++)
        redg_add_f32(&y[b * F_ + f], unpack_sum(acc2[b]));
}

// ---------------------------------------------------------------------------
// Inputs (metadata order): x, mask, kv_idx, kv_key, kv_value,
//                          wq, bq, wk, bk, wv, bv, wo, bo
// ---------------------------------------------------------------------------
extern "C" void kernel_launch(void* const* d_in, const int* in_sizes, int n_in,
                              void* d_out, int out_size)
{
    const float* x        = (const float*)d_in[0];
    const int*   kv_idx   = (const int*)  d_in[2];
    const float* kv_value = (const float*)d_in[4];
    const float* wv       = (const float*)d_in[9];
    const float* bv       = (const float*)d_in[10];
    const float* wo       = (const float*)d_in[11];
    const float* bo       = (const float*)d_in[12];
    float* y = (float*)d_out;

    fused_kernel<<<dim3(NF, NK), TFX>>>(x, kv_idx, kv_value,
                                        wv, bv, wo, bo, y);
}

// round 12
// speedup vs baseline: 1.7305x; 1.1211x over previous
#include <cuda_runtime.h>
#include <cuda_bf16.h>

// Problem constants
#define B_  16
#define C_  4096
#define HD_ 1024   // H*D
#define F_  1024

// Tiling: grid = (NF, NK) = 256 blocks, 128 threads, one f-column per thread
#define NF  8
#define TFX 128
#define NK  32
#define TK  32

// Monotonic per-f-tile counters (never reset -> graph-replay-safe).
__device__ unsigned int g_done[NF];     // zero-init at module load
__device__ unsigned int g_ticket[NF];

__device__ __forceinline__ unsigned ld_acq_u32(const unsigned* p) {
    unsigned v;
    asm volatile("ld.global.acquire.gpu.u32 %0, [%1];" : "=r"(v) : "l"(p));
    return v;
}
__device__ __forceinline__ void redg_add_f32(float* p, float v) {
    asm volatile("red.global.add.f32 [%0], %1;" :: "l"(p), "f"(v) : "memory");
}
__device__ __forceinline__ void ffma2(unsigned long long& d,
                                      unsigned long long a,
                                      unsigned long long b) {
    asm("fma.rn.f32x2 %0, %1, %2, %0;" : "+l"(d) : "l"(a), "l"(b));
}
__device__ __forceinline__ unsigned long long pack2(float lo, float hi) {
    unsigned long long r;
    asm("mov.b64 %0, {%1, %2};" : "=l"(r) : "f"(lo), "f"(hi));
    return r;
}
__device__ __forceinline__ float unpack_sum(unsigned long long v) {
    float lo, hi;
    asm("mov.b64 {%0, %1}, %2;" : "=f"(lo), "=f"(hi) : "l"(v));
    return lo + hi;
}
__device__ __forceinline__ float bfr(float v) {   // bf16 round-trip
    return __bfloat162float(__float2bfloat16(v));
}

// ---------------------------------------------------------------------------
// Single kernel. Attention degenerates (T=1 causal => softmax one-hot at
// rotated position 0) to v_sel[b] = bf16(kv_value[b, start_b]) -- or the
// fresh x@wv+bv row iff idx==0. Then y = v_sel @ wo + bo via split-K.
// Front-end: per-thread direct kv_idx load + single float4 gather, issued
// before anything else; ONE barrier (syncthreads_or) before the FMA loop.
// Epilogue: early-release -- kx==0 block publishes bias into y immediately,
// releases done[fx]; all blocks REDG their partials into y.
// ---------------------------------------------------------------------------
__global__ void __launch_bounds__(TFX)
fused_kernel(const float* __restrict__ x,
             const int*   __restrict__ kv_idx,
             const float* __restrict__ kv_value,
             const float* __restrict__ wv,
             const float* __restrict__ bv,
             const float* __restrict__ wo,
             const float* __restrict__ bo,
             float* __restrict__ y)
{
    const int fx  = blockIdx.x;
    const int kx  = blockIdx.y;
    const int tid = threadIdx.x;
    const int k0  = kx * TK;
    const int f   = fx * TFX + tid;

    __shared__ float    vs[B_][TK];         // bf16-rounded selected v slice
    __shared__ int      s_start[B_];
    __shared__ int      s_new[B_];
    __shared__ unsigned s_target;

    // ---- Critical path first: this thread's single float4 gather ----
    const int  gb      = tid >> 3;          // b this thread gathers for
    const int  gq      = tid & 7;           // float4 index within TK slice
    const int  idxv    = __ldg(&kv_idx[gb]);
    const int  new_idx = idxv + 1;
    const int  start   = (new_idx <= C_) ? 0 : (new_idx & (C_ - 1));
    const bool use_new = (start == (idxv & (C_ - 1)));   // only when idx==0

    float4 gv = make_float4(0.f, 0.f, 0.f, 0.f);
    if (!use_new)
        gv = __ldg(reinterpret_cast<const float4*>(
                 kv_value + ((size_t)gb * C_ + start) * HD_ + k0) + gq);

    // ---- Writer publishes bias into y immediately (overwrites poison) ----
    if (kx == 0) {
        const float bias = __ldg(&bo[f]);
        #pragma unroll
        for (int b = 0; b < B_; b++)
            y[b * F_ + f] = bias;
        __threadfence();            // release bias stores device-wide
    } else if (tid == 0) {
        s_target = atomicAdd(&g_ticket[fx], 1u) / (NK - 1) + 1u;
    }

    // ---- Hoisted wo loads: overlap with gather latency ----
    float w[TK];
    #pragma unroll
    for (int k = 0; k < TK; k++)
        w[k] = __ldg(&wo[(size_t)(k0 + k) * F_ + f]);

    // ---- Store gathered slice (bf16-rounded) + bookkeeping ----
    if (!use_new) {
        float4 r;
        r.x = bfr(gv.x); r.y = bfr(gv.y); r.z = bfr(gv.z); r.w = bfr(gv.w);
        *reinterpret_cast<float4*>(&vs[gb][gq * 4]) = r;
    }
    if (gq == 0) {
        s_new[gb]   = use_new;
        s_start[gb] = start;
    }

    // ONE barrier: vs visible + any_new flag + writer block fully fenced
    const int any_new = __syncthreads_or(use_new ? 1 : 0);

    if (kx == 0 && tid == 0)
        atomicAdd(&g_done[fx], 1u);          // release after block fenced

    if (any_new) {      // never taken for this input; kept for correctness
        for (int b = 0; b < B_; b++) {
            if (s_new[b] && tid < TK) {
                const int j = k0 + tid;
                float acc = bv[j];
                for (int ff = 0; ff < F_; ff++)
                    acc = fmaf(__ldg(&x[b * F_ + ff]),
                               __ldg(&wv[(size_t)ff * HD_ + j]), acc);
                vs[b][tid] = bfr(acc);
            }
        }
        __syncthreads();
    }

    // ---- Main loop: pure LDS + packed f32x2 FMA (wo already in regs) ----
    unsigned long long acc2[B_];
    #pragma unroll
    for (int b = 0; b < B_; b++) acc2[b] = 0ull;

    #pragma unroll
    for (int k4 = 0; k4 < TK; k4 += 4) {
        const unsigned long long wA = pack2(w[k4 + 0], w[k4 + 1]);
        const unsigned long long wB = pack2(w[k4 + 2], w[k4 + 3]);
        #pragma unroll
        for (int b = 0; b < B_; b++) {
            const float4 v = *reinterpret_cast<const float4*>(&vs[b][k4]);
            ffma2(acc2[b], pack2(v.x, v.y), wA);
            ffma2(acc2[b], pack2(v.z, v.w), wB);
        }
    }

    // ---- Epilogue: ensure bias published, then fire REDG partials ----
    if (kx != 0) {
        if (tid == 0) {
            while (ld_acq_u32(&g_done[fx]) < s_target)   // usually 1 read
                __nanosleep(32);
        }
        __syncthreads();            // all threads ordered after acquire
    }
    // Writer: same-thread store->red on same address is program-ordered.
    #pragma unroll
    for (int b = 0; b < B_; b++)
        redg_add_f32(&y[b * F_ + f], unpack_sum(acc2[b]));
}

// ---------------------------------------------------------------------------
// Inputs (metadata order): x, mask, kv_idx, kv_key, kv_value,
//                          wq, bq, wk, bk, wv, bv, wo, bo
// ---------------------------------------------------------------------------
extern "C" void kernel_launch(void* const* d_in, const int* in_sizes, int n_in,
                              void* d_out, int out_size)
{
    const float* x        = (const float*)d_in[0];
    const int*   kv_idx   = (const int*)  d_in[2];
    const float* kv_value = (const float*)d_in[4];
    const float* wv       = (const float*)d_in[9];
    const float* bv       = (const float*)d_in[10];
    const float* wo       = (const float*)d_in[11];
    const float* bo       = (const float*)d_in[12];
    float* y = (float*)d_out;

    fused_kernel<<<dim3(NF, NK), TFX>>>(x, kv_idx, kv_value,
                                        wv, bv, wo, bo, y);
}